// round 17
// baseline (speedup 1.0000x reference)
#include <cuda_runtime.h>
#include <cuda_fp16.h>
#include <cstdint>
#include <math.h>

#define DIM 128
#define TILE 128
#define BMAX 8192
#define NTMAX 64
#define TPB 4                  // B-tiles per CTA; A tile stays resident
#define LDW 68                 // smem row stride in words (272B)

__device__ float g_nsk[BMAX];
__device__ float g_nim[BMAX];
__device__ uint32_t g_skh[BMAX * 64];                     // f16x2-packed rows
__device__ uint32_t g_imh[BMAX * 64];
__device__ float g_partial[(size_t)BMAX * NTMAX * 2];     // per (row, bn, wn-half)
__device__ float g_diag[BMAX];                            // exact fp32 diagonal distance
__device__ float g_bsum[NTMAX];                           // per-bm row-block sums
__device__ unsigned g_cnt_bm[NTMAX];                      // per-bm completion counters
__device__ unsigned g_cnt2;                               // bm-winner counter

static __device__ __forceinline__ uint32_t s2u(const void* p) {
    uint32_t a;
    asm("{ .reg .u64 t; cvta.to.shared.u64 t, %1; cvt.u32.u64 %0, t; }" : "=r"(a) : "l"(p));
    return a;
}
static __device__ __forceinline__ void cpa16(uint32_t dst, const void* src) {
    asm volatile("cp.async.cg.shared.global [%0], [%1], 16;" :: "r"(dst), "l"(src) : "memory");
}
#define CP_COMMIT() asm volatile("cp.async.commit_group;" ::: "memory")
#define CP_WAIT0()  asm volatile("cp.async.wait_group 0;" ::: "memory")
#define CP_WAIT1()  asm volatile("cp.async.wait_group 1;" ::: "memory")

// f16-accumulate legacy HMMA: 2-reg packed accumulator
static __device__ __forceinline__ void mma16h(uint32_t* c, const uint32_t* a, const uint32_t* b) {
    asm("mma.sync.aligned.m16n8k16.row.col.f16.f16.f16.f16 "
        "{%0,%1}, {%2,%3,%4,%5}, {%6,%7}, {%0,%1};"
        : "+r"(c[0]), "+r"(c[1])
        : "r"(a[0]), "r"(a[1]), "r"(a[2]), "r"(a[3]), "r"(b[0]), "r"(b[1]));
}
#define LDSM4(r0, r1, r2, r3, addr)                                            \
    asm volatile("ldmatrix.sync.aligned.m8n8.x4.shared.b16 {%0,%1,%2,%3}, [%4];" \
                 : "=r"(r0), "=r"(r1), "=r"(r2), "=r"(r3) : "r"(addr))

// ---------------------------------------------------------------------------
// Single-pass prep: one warp per row reads sk+im once -> both f16 packs,
// both fp32 norms, exact fp32 diagonal. Also resets completion counters.
// ---------------------------------------------------------------------------
__global__ void prep_kernel(const float* __restrict__ sk,
                            const float* __restrict__ im, int B) {
    if (blockIdx.x == 0) {
        if (threadIdx.x < NTMAX) g_cnt_bm[threadIdx.x] = 0u;
        if (threadIdx.x == NTMAX) g_cnt2 = 0u;
    }
    int row = (blockIdx.x * blockDim.x + threadIdx.x) >> 5;
    int lane = threadIdx.x & 31;
    if (row >= B) return;

    float4 a = ((const float4*)(sk + (size_t)row * DIM))[lane];
    float4 b = ((const float4*)(im + (size_t)row * DIM))[lane];

    __half2 ha0 = __floats2half2_rn(a.x, a.y);
    __half2 ha1 = __floats2half2_rn(a.z, a.w);
    g_skh[row * 64 + lane * 2]     = *(uint32_t*)&ha0;
    g_skh[row * 64 + lane * 2 + 1] = *(uint32_t*)&ha1;
    __half2 hb0 = __floats2half2_rn(b.x, b.y);
    __half2 hb1 = __floats2half2_rn(b.z, b.w);
    g_imh[row * 64 + lane * 2]     = *(uint32_t*)&hb0;
    g_imh[row * 64 + lane * 2 + 1] = *(uint32_t*)&hb1;

    float sa = a.x * a.x + a.y * a.y + a.z * a.z + a.w * a.w;
    float sb = b.x * b.x + b.y * b.y + b.z * b.z + b.w * b.w;
    float dx = a.x - b.x, dy = a.y - b.y, dz = a.z - b.z, dw = a.w - b.w;
    float sd = dx * dx + dy * dy + dz * dz + dw * dw;
#pragma unroll
    for (int o = 16; o; o >>= 1) {
        sa += __shfl_xor_sync(0xffffffffu, sa, o);
        sb += __shfl_xor_sync(0xffffffffu, sb, o);
        sd += __shfl_xor_sync(0xffffffffu, sd, o);
    }
    if (lane == 0) {
        g_nsk[row] = sa;
        g_nim[row] = sb;
        g_diag[row] = sqrtf(sd);
    }
}

// ---------------------------------------------------------------------------
// Software-pipelined f16 MMA (f16 acc) + fused distance/exp epilogue, occ 2.
// Fragment loads via ldmatrix.x4: 6 LDSM per k-step instead of 24 scalar LDS.
// Epilogue of tile t-1 interleaved per k-step; fused last-CTA reduction tail.
// ---------------------------------------------------------------------------
__global__ void __launch_bounds__(256, 2)
dist_mma(float* __restrict__ out, int nt, int out_size) {
    extern __shared__ uint32_t smw[];
    const uint32_t sbase = s2u(smw);
    const uint32_t NORM_OFF = 3u * 128u * LDW;            // word offset of norm buffer
    float* nsm = (float*)(smw + NORM_OFF);                // 4*128 floats
    __shared__ unsigned s_rank;

    const int tid = threadIdx.x;
    const int wid = tid >> 5;
    const int lane = tid & 31;
    const int g = lane >> 2;
    const int t = lane & 3;
    const int wm = wid & 3;        // m-block: 32 rows
    const int wn = wid >> 2;       // n-block: 64 cols

    const int ntg = nt / TPB;
    const int bm = blockIdx.x / ntg;
    const int bn0 = (blockIdx.x % ntg) * TPB;

    // ---- prologue: A, B0, norms (group 0); B1 prefetch (group 1) ----
    {
        const uint32_t* Ag = g_skh + (size_t)bm * TILE * 64;
        const uint32_t* Bg = g_imh + (size_t)bn0 * TILE * 64;
#pragma unroll
        for (int it = 0; it < 8; it++) {
            int c = it * 256 + tid;          // 0..2047 16B-chunks
            int row = c >> 4, ch = c & 15;
            uint32_t doff = (uint32_t)row * 272 + (uint32_t)ch * 16;
            cpa16(sbase + doff, Ag + row * 64 + ch * 4);
            cpa16(sbase + 128 * LDW * 4 + doff, Bg + row * 64 + ch * 4);
        }
        if (tid < 128)
            cpa16(sbase + NORM_OFF * 4 + (uint32_t)tid * 16, g_nim + (size_t)bn0 * TILE + tid * 4);
        CP_COMMIT();
        const uint32_t* Bg1 = g_imh + (size_t)(bn0 + 1) * TILE * 64;
#pragma unroll
        for (int it = 0; it < 8; it++) {
            int c = it * 256 + tid;
            int row = c >> 4, ch = c & 15;
            cpa16(sbase + 2 * 128 * LDW * 4 + (uint32_t)row * 272 + (uint32_t)ch * 16,
                  Bg1 + row * 64 + ch * 4);
        }
        CP_COMMIT();
        CP_WAIT1();
    }
    __syncthreads();

    float nr[2][2];
#pragma unroll
    for (int mt = 0; mt < 2; mt++)
#pragma unroll
        for (int h = 0; h < 2; h++)
            nr[mt][h] = g_nsk[bm * TILE + wm * 32 + mt * 16 + h * 8 + g];

    // ldmatrix per-lane base addresses (bytes)
    // A: lanes 0-15 -> rows 0-15 (+0B), lanes 16-31 -> rows 0-15 (+16B = k high)
    const uint32_t a_lm = sbase + (uint32_t)(wm * 32 + (lane & 15)) * 272
                          + (uint32_t)(lane >> 4) * 16;
    // B: row = (l&7) + ((l>>4)&1)*8 ; koff = ((l>>3)&1)*16
    const uint32_t b_lm_rel = (uint32_t)(wn * 64 + (lane & 7) + ((lane >> 4) & 1) * 8) * 272
                              + (uint32_t)((lane >> 3) & 1) * 16;

    uint32_t acc[2][2][8][2];      // [buf][mt][nb][h]  packed f16x2
    float rs[2][2];

#pragma unroll
    for (int tt = 0; tt <= TPB; tt++) {
        const bool do_main = (tt < TPB);
        const bool do_epi = (tt > 0);
        const int nbuf = tt & 1;
        const int bn_old = bn0 + tt - 1;

        // prefetch B[tt+1] into buffer (tt+1)&1
        if (tt + 1 < TPB) {
            const uint32_t* Bg = g_imh + (size_t)(bn0 + tt + 1) * TILE * 64;
            uint32_t dbuf = sbase + (1 + ((tt + 1) & 1)) * 128 * LDW * 4;
#pragma unroll
            for (int it = 0; it < 8; it++) {
                int c = it * 256 + tid;
                int row = c >> 4, ch = c & 15;
                cpa16(dbuf + (uint32_t)row * 272 + (uint32_t)ch * 16, Bg + row * 64 + ch * 4);
            }
            CP_COMMIT();
        }

        uint32_t (*accN)[8][2] = acc[nbuf];
        uint32_t (*accO)[8][2] = acc[nbuf ^ 1];
        const uint32_t b_lm = sbase + (uint32_t)(1 + (tt & 1)) * 128 * LDW * 4 + b_lm_rel;

        if (do_main) {
#pragma unroll
            for (int mt = 0; mt < 2; mt++)
#pragma unroll
                for (int nb = 0; nb < 8; nb++) {
                    accN[mt][nb][0] = 0u;
                    accN[mt][nb][1] = 0u;
                }
        }
        if (do_epi) { rs[0][0] = rs[0][1] = rs[1][0] = rs[1][1] = 0.f; }

        // 8 k-steps of 16; 1 epilogue chunk (nb=ks) of the previous tile per step
#pragma unroll
        for (int ks = 0; ks < 8; ks++) {
            if (do_main) {
                const uint32_t ko = (uint32_t)ks * 32;    // 16 f16 = 32 bytes
                uint32_t a[2][4], b[8][2];
                LDSM4(a[0][0], a[0][1], a[0][2], a[0][3], a_lm + ko);
                LDSM4(a[1][0], a[1][1], a[1][2], a[1][3], a_lm + 16 * 272 + ko);
#pragma unroll
                for (int j = 0; j < 4; j++) {
                    LDSM4(b[2 * j][0], b[2 * j][1], b[2 * j + 1][0], b[2 * j + 1][1],
                          b_lm + (uint32_t)j * (16 * 272) + ko);
                }
#pragma unroll
                for (int mt = 0; mt < 2; mt++)
#pragma unroll
                    for (int nb = 0; nb < 8; nb++) mma16h(accN[mt][nb], a[mt], b[nb]);
            }
            if (do_epi) {
                float2 nc = *(const float2*)&nsm[(tt - 1) * 128 + wn * 64 + ks * 8 + t * 2];
#pragma unroll
                for (int mt = 0; mt < 2; mt++) {
#pragma unroll
                    for (int h = 0; h < 2; h++) {
                        float2 dot = __half22float2(*(__half2*)&accO[mt][ks][h]);
                        float base = nr[mt][h];
                        float sq0 = fmaxf(fmaf(-2.f, dot.x, base + nc.x), 0.f);
                        float sq1 = fmaxf(fmaf(-2.f, dot.y, base + nc.y), 0.f);
                        float d0, d1, e0, e1;
                        asm("sqrt.approx.f32 %0, %1;" : "=f"(d0) : "f"(sq0));
                        asm("sqrt.approx.f32 %0, %1;" : "=f"(d1) : "f"(sq1));
                        asm("ex2.approx.f32 %0, %1;" : "=f"(e0) : "f"(d0 * -1.4426950408889634f));
                        asm("ex2.approx.f32 %0, %1;" : "=f"(e1) : "f"(d1 * -1.4426950408889634f));
                        rs[mt][h] += e0 + e1;
                    }
                }
            }
        }

        if (do_epi) {
#pragma unroll
            for (int mt = 0; mt < 2; mt++) {
#pragma unroll
                for (int h = 0; h < 2; h++) {
                    float v = rs[mt][h];
                    v += __shfl_xor_sync(0xffffffffu, v, 1);
                    v += __shfl_xor_sync(0xffffffffu, v, 2);
                    if (t == 0) {
                        int r_local = wm * 32 + mt * 16 + h * 8 + g;
                        g_partial[((size_t)(bm * TILE + r_local) * nt + bn_old) * 2 + wn] = v;
                    }
                }
            }
        }

        if (do_main) {
            CP_WAIT0();
            __syncthreads();
        }
    }

    // ---- fused reduction tail ----
    __threadfence();
    __syncthreads();
    if (tid == 0) s_rank = atomicAdd(&g_cnt_bm[bm], 1u);
    __syncthreads();
    if (s_rank == (unsigned)(ntg - 1)) {
        float rv = 0.f;
        if (tid < TILE) {
            int row = bm * TILE + tid;
            const float* p = g_partial + (size_t)row * nt * 2;
            float s = 0.f;
            for (int k = 0; k < 2 * nt; k++) s += p[k];   // fixed order
            rv = logf(s) + g_diag[row];
        }
        float* red = (float*)smw;    // reuse dynamic smem
        red[tid] = rv;
        __syncthreads();
        for (int o = 128; o; o >>= 1) {
            if (tid < o) red[tid] += red[tid + o];
            __syncthreads();
        }
        if (tid == 0) {
            g_bsum[bm] = red[0];
            __threadfence();
            unsigned done = atomicAdd(&g_cnt2, 1u);
            if (done == (unsigned)(nt - 1)) {
                float s = 0.f;
                for (int b = 0; b < nt; b++) s += g_bsum[b];   // fixed order
                float loss = s / (float)(nt * TILE);
                for (int k = 0; k < out_size; k++) out[k] = loss;
            }
        }
    }
}

extern "C" void kernel_launch(void* const* d_in, const int* in_sizes, int n_in,
                              void* d_out, int out_size) {
    const float* sk = (const float*)d_in[0];
    const float* im = (const float*)d_in[1];
    float* out = (float*)d_out;

    int B = in_sizes[0] / DIM;   // 8192
    int nt = B / TILE;           // 64

    prep_kernel<<<B / 8, 256>>>(sk, im, B);

    static const int SMEM_BYTES = (3 * 128 * LDW + 4 * 128) * 4;   // 106496
    cudaFuncSetAttribute(dist_mma, cudaFuncAttributeMaxDynamicSharedMemorySize, SMEM_BYTES);
    int ncta = nt * (nt / TPB);  // 1024
    dist_mma<<<ncta, 256, SMEM_BYTES>>>(out, nt, out_size);
}